// round 4
// baseline (speedup 1.0000x reference)
#include <cuda_runtime.h>
#include <math_constants.h>

// out = minmax_normalize( bicubic_up2x( LL[:, 0:8] ) )
// All other iqwt terms carry sum(gh)=sum(fl)=sum(fh)=0 (f32 residue < 3e-7);
// the surviving sg^2 scalar cancels in the min-max normalization.
//
// memset node: g_red = {minEnc, minEnc(-v)} sentinels, both 0xFFFFFFFF.
// Pass 1: upsample (discard), block min/max -> 2 atomics.
// Pass 2: recompute (input L2-resident), fused normalize, streaming stores.

#define THREADS 256
#define TILE_J  8             // input rows per tile -> 16 output rows
#define IN_ROWS (TILE_J + 4)  // 12 input rows incl. halo
#define SMEM_W  260           // 256 cols + 2 halo each side
#define N_IN    256
#define N_OUT   512
#define N_IMG   64            // 8 batches * 8 channels (lglg slice)
#define TILES_PER_IMG (N_IN / TILE_J)   // 32
#define GRID (N_IMG * TILES_PER_IMG)    // 2048

// bicubic a=-0.75, src = 0.5*i - 0.25
#define WE0 (-0.03515625f)
#define WE1 ( 0.26171875f)
#define WE2 ( 0.87890625f)
#define WE3 (-0.10546875f)
#define WO0 (-0.10546875f)
#define WO1 ( 0.87890625f)
#define WO2 ( 0.26171875f)
#define WO3 (-0.03515625f)

__device__ unsigned int g_red[2];   // [0]=min(enc(v)), [1]=min(enc(-v))

__device__ __forceinline__ unsigned int encf(float f) {
    unsigned int u = __float_as_uint(f);
    return (u & 0x80000000u) ? ~u : (u | 0x80000000u);
}
__device__ __forceinline__ float decf(unsigned int e) {
    unsigned int u = (e & 0x80000000u) ? (e ^ 0x80000000u) : ~e;
    return __uint_as_float(u);
}

template <bool WRITE>
__global__ __launch_bounds__(THREADS)
void qwt_up_kernel(const float* __restrict__ LL, float* __restrict__ out) {
    __shared__ float s[IN_ROWS][SMEM_W];

    const int tid  = threadIdx.x;
    const int img  = blockIdx.x / TILES_PER_IMG;   // 0..63
    const int tile = blockIdx.x % TILES_PER_IMG;   // 0..31
    const int b    = img >> 3;
    const int ch   = img & 7;                      // lglg = LL channels 0..7
    const float* __restrict__ src = LL + (size_t)(b * 32 + ch) * (N_IN * N_IN);
    const int jbase = tile * TILE_J;

    float scale = 1.0f, bias = 0.0f;
    if (WRITE) {
        const float mn =  decf(g_red[0]);
        const float mx = -decf(g_red[1]);
        scale = 1.0f / (mx - mn);
        bias  = -mn * scale;
    }

    // Coalesced fill: thread tid owns input column tid; edge threads write
    // the 2-wide replicate halo. All 12 LDGs issue back-to-back (high MLP).
#pragma unroll
    for (int rr = 0; rr < IN_ROWS; rr++) {
        int gr = jbase - 2 + rr; gr = min(max(gr, 0), N_IN - 1);
        const float v = __ldg(src + gr * N_IN + tid);
        s[rr][tid + 2] = v;
        if (tid == 0)        { s[rr][0]   = v; s[rr][1]   = v; }
        if (tid == N_IN - 1) { s[rr][258] = v; s[rr][259] = v; }
    }
    __syncthreads();

    // Horizontal pass, fully batched: 60 LDS issued with maximum MLP.
    const int k = tid;
    float he[IN_ROWS], ho[IN_ROWS];
#pragma unroll
    for (int rr = 0; rr < IN_ROWS; rr++) {
        const float z0 = s[rr][k + 0], z1 = s[rr][k + 1], z2 = s[rr][k + 2];
        const float z3 = s[rr][k + 3], z4 = s[rr][k + 4];
        he[rr] = WE0 * z0 + WE1 * z1 + WE2 * z2 + WE3 * z3;
        ho[rr] = WO0 * z1 + WO1 * z2 + WO2 * z3 + WO3 * z4;
    }

    float lmin =  CUDART_INF_F;
    float lmax = -CUDART_INF_F;
    const size_t obase = (size_t)img * (N_OUT * N_OUT);
    const int I0 = tile * (2 * TILE_J);

#pragma unroll
    for (int jj = 0; jj < TILE_J; jj++) {
        const float ee = WE0 * he[jj]     + WE1 * he[jj + 1] + WE2 * he[jj + 2] + WE3 * he[jj + 3];
        const float eo = WE0 * ho[jj]     + WE1 * ho[jj + 1] + WE2 * ho[jj + 2] + WE3 * ho[jj + 3];
        const float oe = WO0 * he[jj + 1] + WO1 * he[jj + 2] + WO2 * he[jj + 3] + WO3 * he[jj + 4];
        const float oo = WO0 * ho[jj + 1] + WO1 * ho[jj + 2] + WO2 * ho[jj + 3] + WO3 * ho[jj + 4];

        if (WRITE) {
            const int I = I0 + 2 * jj;
            float2 v0 = make_float2(fmaf(ee, scale, bias), fmaf(eo, scale, bias));
            float2 v1 = make_float2(fmaf(oe, scale, bias), fmaf(oo, scale, bias));
            __stcs(reinterpret_cast<float2*>(out + obase + (size_t)I * N_OUT + 2 * k), v0);
            __stcs(reinterpret_cast<float2*>(out + obase + (size_t)(I + 1) * N_OUT + 2 * k), v1);
        } else {
            lmin = fminf(lmin, fminf(fminf(ee, eo), fminf(oe, oo)));
            lmax = fmaxf(lmax, fmaxf(fmaxf(ee, eo), fmaxf(oe, oo)));
        }
    }

    if (!WRITE) {
#pragma unroll
        for (int off = 16; off > 0; off >>= 1) {
            lmin = fminf(lmin, __shfl_xor_sync(0xFFFFFFFFu, lmin, off));
            lmax = fmaxf(lmax, __shfl_xor_sync(0xFFFFFFFFu, lmax, off));
        }
        __shared__ float wmin[THREADS / 32], wmax[THREADS / 32];
        const int w = tid >> 5, l = tid & 31;
        if (l == 0) { wmin[w] = lmin; wmax[w] = lmax; }
        __syncthreads();
        if (tid == 0) {
            float m = wmin[0], M = wmax[0];
#pragma unroll
            for (int i = 1; i < THREADS / 32; i++) {
                m = fminf(m, wmin[i]);
                M = fmaxf(M, wmax[i]);
            }
            atomicMin(&g_red[0], encf(m));
            atomicMin(&g_red[1], encf(-M));
        }
    }
}

extern "C" void kernel_launch(void* const* d_in, const int* in_sizes, int n_in,
                              void* d_out, int out_size) {
    const float* LL = (const float*)d_in[0];
    float* out = (float*)d_out;
    (void)in_sizes; (void)n_in; (void)out_size;

    static unsigned int* red_ptr = nullptr;
    if (!red_ptr) cudaGetSymbolAddress((void**)&red_ptr, g_red);

    cudaMemsetAsync(red_ptr, 0xFF, 2 * sizeof(unsigned int));
    qwt_up_kernel<false><<<GRID, THREADS>>>(LL, out);  // min/max pass
    qwt_up_kernel<true ><<<GRID, THREADS>>>(LL, out);  // normalize + write pass
}

// round 5
// speedup vs baseline: 1.2218x; 1.2218x over previous
#include <cuda_runtime.h>
#include <math_constants.h>

// out = minmax_normalize( bicubic_up2x( LL[:, 0:8] ) )
// All other iqwt terms carry sum(gh)=sum(fl)=sum(fh)=0 (f32 residue < 3e-7);
// the surviving sg^2 scalar cancels in the min-max normalization.
//
// memset node: g_red sentinels (both 0xFFFFFFFF).
// Pass 1: upsample into 32 register accumulators/thread, min/max -> atomics.
// Pass 2: recompute (input L2-resident), fused normalize, float4 stores.

#define THREADS 256
#define TILE_J  8             // input rows per block -> 16 output rows
#define IN_ROWS 12            // 8 + 4 halo
#define SMEM_W  264           // 2 halo + 256 + 2 halo + pad (16B-multiple row)
#define N_IN    256
#define N_OUT   512
#define N_IMG   64
#define TILES_PER_IMG 32
#define GRID (N_IMG * TILES_PER_IMG)   // 2048

// bicubic a=-0.75, src = 0.5*i - 0.25
#define WE0 (-0.03515625f)
#define WE1 ( 0.26171875f)
#define WE2 ( 0.87890625f)
#define WE3 (-0.10546875f)
#define WO0 (-0.10546875f)
#define WO1 ( 0.87890625f)
#define WO2 ( 0.26171875f)
#define WO3 (-0.03515625f)

__device__ unsigned int g_red[2];   // [0]=min(enc(v)), [1]=min(enc(-v))

__device__ __forceinline__ unsigned int encf(float f) {
    unsigned int u = __float_as_uint(f);
    return (u & 0x80000000u) ? ~u : (u | 0x80000000u);
}
__device__ __forceinline__ float decf(unsigned int e) {
    unsigned int u = (e & 0x80000000u) ? (e ^ 0x80000000u) : ~e;
    return __uint_as_float(u);
}

template <bool WRITE>
__global__ __launch_bounds__(THREADS)
void qwt_up_kernel(const float* __restrict__ LL, float* __restrict__ out) {
    __shared__ float s[IN_ROWS][SMEM_W];

    const int t    = threadIdx.x;
    const int img  = blockIdx.x >> 5;        // 0..63
    const int tile = blockIdx.x & 31;        // 0..31
    const int b    = img >> 3;
    const int ch   = img & 7;                // lglg = LL channels 0..7
    const float* __restrict__ src = LL + (size_t)(b * 32 + ch) * (N_IN * N_IN);
    const int jbase = tile * TILE_J;

    float scale = 1.0f, bias = 0.0f;
    if (WRITE) {
        const float mn =  decf(g_red[0]);
        const float mx = -decf(g_red[1]);
        scale = 1.0f / (mx - mn);
        bias  = -mn * scale;
    }

    // ---- Fill 12x260 tile. Input col c -> smem col c+2 (this realigns the
    // filter windows to 16B). 768 float4 loads, 3 per thread, coalesced.
#pragma unroll
    for (int i = 0; i < 3; i++) {
        const int f  = t + i * THREADS;      // 0..767
        const int rr = f >> 6;               // smem row 0..11
        const int qc = f & 63;               // float4 index in row
        int gr = jbase - 2 + rr; gr = min(max(gr, 0), N_IN - 1);
        const float4 v = *reinterpret_cast<const float4*>(src + gr * N_IN + 4 * qc);
        float2* p = reinterpret_cast<float2*>(&s[rr][4 * qc + 2]);
        p[0] = make_float2(v.x, v.y);
        p[1] = make_float2(v.z, v.w);
        if (qc == 0)  { s[rr][0]   = v.x; s[rr][1]   = v.x; }  // left replicate
        if (qc == 63) { s[rr][258] = v.w; s[rr][259] = v.w; }  // right replicate
    }
    __syncthreads();

    // ---- Compute. Thread = (col-quad q, row-group g).
    // q handles output cols 8q..8q+7; g handles output row-pairs 2g, 2g+1
    // (block-local), i.e. output rows 4g..4g+3.
    const int q = t & 63;
    const int g = t >> 6;

    float acc[4][8];                 // [out row a = 4g+a][out col 8q+c]
#pragma unroll
    for (int a = 0; a < 4; a++)
#pragma unroll
        for (int c = 0; c < 8; c++) acc[a][c] = 0.0f;

    const float WEv[4] = {WE0, WE1, WE2, WE3};
    const float WOv[4] = {WO0, WO1, WO2, WO3};

#pragma unroll
    for (int r = 0; r < 6; r++) {            // h rows 2g..2g+5
        const float* row = &s[2 * g + r][4 * q];     // 16B-aligned
        const float4 a4 = *reinterpret_cast<const float4*>(row);
        const float4 b4 = *reinterpret_cast<const float4*>(row + 4);
        const float z[8] = {a4.x, a4.y, a4.z, a4.w, b4.x, b4.y, b4.z, b4.w};
        float he[4], ho[4];
#pragma unroll
        for (int p = 0; p < 4; p++) {
            he[p] = WE0 * z[p]     + WE1 * z[p + 1] + WE2 * z[p + 2] + WE3 * z[p + 3];
            ho[p] = WO0 * z[p + 1] + WO1 * z[p + 2] + WO2 * z[p + 3] + WO3 * z[p + 4];
        }
#pragma unroll
        for (int jj = 0; jj < 2; jj++) {
            const int de = r - jj;           // even-out-row tap index
            if (de >= 0 && de < 4) {
                const float w = WEv[de];     // compile-time immediate
#pragma unroll
                for (int p = 0; p < 4; p++) {
                    acc[2 * jj][2 * p]     += w * he[p];
                    acc[2 * jj][2 * p + 1] += w * ho[p];
                }
            }
            const int dd = r - jj - 1;       // odd-out-row tap index
            if (dd >= 0 && dd < 4) {
                const float w = WOv[dd];
#pragma unroll
                for (int p = 0; p < 4; p++) {
                    acc[2 * jj + 1][2 * p]     += w * he[p];
                    acc[2 * jj + 1][2 * p + 1] += w * ho[p];
                }
            }
        }
    }

    if (WRITE) {
        const size_t obase = (size_t)img * (N_OUT * N_OUT) + 8 * q;
        const int rbase = tile * 16 + 4 * g;
#pragma unroll
        for (int a = 0; a < 4; a++) {
            float4 v0, v1;
            v0.x = fmaf(acc[a][0], scale, bias); v0.y = fmaf(acc[a][1], scale, bias);
            v0.z = fmaf(acc[a][2], scale, bias); v0.w = fmaf(acc[a][3], scale, bias);
            v1.x = fmaf(acc[a][4], scale, bias); v1.y = fmaf(acc[a][5], scale, bias);
            v1.z = fmaf(acc[a][6], scale, bias); v1.w = fmaf(acc[a][7], scale, bias);
            float* rp = out + obase + (size_t)(rbase + a) * N_OUT;
            *reinterpret_cast<float4*>(rp)     = v0;
            *reinterpret_cast<float4*>(rp + 4) = v1;
        }
    } else {
        float lmin =  CUDART_INF_F;
        float lmax = -CUDART_INF_F;
#pragma unroll
        for (int a = 0; a < 4; a++)
#pragma unroll
            for (int c = 0; c < 8; c++) {
                lmin = fminf(lmin, acc[a][c]);
                lmax = fmaxf(lmax, acc[a][c]);
            }
#pragma unroll
        for (int off = 16; off > 0; off >>= 1) {
            lmin = fminf(lmin, __shfl_xor_sync(0xFFFFFFFFu, lmin, off));
            lmax = fmaxf(lmax, __shfl_xor_sync(0xFFFFFFFFu, lmax, off));
        }
        __shared__ float wmin[THREADS / 32], wmax[THREADS / 32];
        const int w = t >> 5, l = t & 31;
        if (l == 0) { wmin[w] = lmin; wmax[w] = lmax; }
        __syncthreads();
        if (t == 0) {
            float m = wmin[0], M = wmax[0];
#pragma unroll
            for (int i = 1; i < THREADS / 32; i++) {
                m = fminf(m, wmin[i]);
                M = fmaxf(M, wmax[i]);
            }
            atomicMin(&g_red[0], encf(m));
            atomicMin(&g_red[1], encf(-M));
        }
    }
}

extern "C" void kernel_launch(void* const* d_in, const int* in_sizes, int n_in,
                              void* d_out, int out_size) {
    const float* LL = (const float*)d_in[0];
    float* out = (float*)d_out;
    (void)in_sizes; (void)n_in; (void)out_size;

    static unsigned int* red_ptr = nullptr;
    if (!red_ptr) cudaGetSymbolAddress((void**)&red_ptr, g_red);

    cudaMemsetAsync(red_ptr, 0xFF, 2 * sizeof(unsigned int));
    qwt_up_kernel<false><<<GRID, THREADS>>>(LL, out);  // min/max pass
    qwt_up_kernel<true ><<<GRID, THREADS>>>(LL, out);  // normalize + write pass
}